// round 16
// baseline (speedup 1.0000x reference)
#include <cuda_runtime.h>
#include <cstdint>

#define NC 256
#define NH 256
#define NW 256
#define NBOX 100
#define SLICES 8                       // writer slices per channel -> 2048 blocks
#define ROWS_PER_SLICE (NH / SLICES)   // 32
#define TILE_F4 (ROWS_PER_SLICE * NW / 4)   // 2048 float4 per block

// ---------------------------------------------------------------------------
// ONE kernel, 2048 independent blocks (8 per channel). Each block redundantly
// computes its channel's 4 coefficients (cheap prologue: coalesced box staging,
// 400 gathers over 256 threads, shuffle reduce), then streams its 32-row slice
// at the L2 write cap. No inter-block sync, one graph node.
//   out[c,h,w] = w*(w*A - B1) + h*(h*A - B2) + D
// nonzero(size=100, fill=0) == each selected box once + (100-cnt) copies of box 0.
// ---------------------------------------------------------------------------
__global__ __launch_bounds__(256)
void fused_kernel(const float* __restrict__ boxes,
                  const float* __restrict__ scores,
                  const float* __restrict__ feat,
                  float4* __restrict__ out) {
    __shared__ float  s_box[NBOX * 24];    // staged box corners (9.6 KB)
    __shared__ float4 s_kv[NBOX];          // per-box (am, am*2cx, am*2cy, am*r2)
    __shared__ float  s_w[NBOX][4];        // bilinear weights
    __shared__ int    s_o[NBOX][4];        // gather offsets
    __shared__ float4 red[8];              // per-warp partials
    __shared__ float4 s_coef;
    __shared__ int    s_pc[4];

    const int tid   = threadIdx.x;
    const int c     = blockIdx.x >> 3;
    const int slice = blockIdx.x & 7;

    // ---- Phase A: scores ballot (warps 0-3) + cooperative box staging ----
    if (tid < 128) {
        int m = (tid < NBOX) ? ((scores[tid] > 0.0f) ? 1 : 0) : 0;
        unsigned bal = __ballot_sync(0xffffffffu, m);
        if ((tid & 31) == 0) s_pc[tid >> 5] = __popc(bal);
    }
    {   // coalesced: 600 float4 staged by all 256 threads
        const float4* src = (const float4*)boxes;
        float4*       dst = (float4*)s_box;
        #pragma unroll
        for (int i = tid; i < NBOX * 6; i += 256) dst[i] = src[i];
    }
    __syncthreads();
    const int cnt = s_pc[0] + s_pc[1] + s_pc[2] + s_pc[3];

    // ---- Phase B: per-box params from smem (threads 0..99) ----
    if (tid < NBOX) {
        const float* b = s_box + tid * 24;
        float lx = b[0], rx = b[0], ly = b[1], ry = b[1];
        #pragma unroll
        for (int k = 1; k < 8; k++) {
            float x = b[3 * k], y = b[3 * k + 1];
            lx = fminf(lx, x); rx = fmaxf(rx, x);
            ly = fminf(ly, y); ry = fmaxf(ry, y);
        }
        float cx  = ((lx + rx) * 0.5f + 128.0f) / 160.0f;
        float cy  = ((ly + ry) * 0.5f + 128.0f) / 160.0f;
        float bev = ((ry - ly) / 160.0f) * ((rx - lx) / 160.0f);
        float a   = 1.0f / (2.0f * bev * bev);

        float m    = (scores[tid] > 0.0f) ? 1.0f : 0.0f;
        float mult = (tid == 0) ? (m + (float)(NBOX - cnt)) : m;
        float am   = a * mult * (1.0f / (float)NBOX);
        s_kv[tid]  = make_float4(am, am * 2.0f * cx, am * 2.0f * cy,
                                 am * (cx * cx + cy * cy));

        // bilinear grid_sample (zero pad, align_corners=False)
        float ix = ((cx + 1.0f) * (float)NW - 1.0f) * 0.5f;
        float iy = ((cy + 1.0f) * (float)NH - 1.0f) * 0.5f;
        float x0f = floorf(ix), y0f = floorf(iy);
        float wx1 = ix - x0f, wx0 = 1.0f - wx1;
        float wy1 = iy - y0f, wy0 = 1.0f - wy1;
        int x0 = (int)x0f, y0 = (int)y0f, x1 = x0 + 1, y1 = y0 + 1;
        bool vx0 = (x0 >= 0 && x0 < NW), vx1 = (x1 >= 0 && x1 < NW);
        bool vy0 = (y0 >= 0 && y0 < NH), vy1 = (y1 >= 0 && y1 < NH);
        int px0 = min(max(x0, 0), NW - 1), px1 = min(max(x1, 0), NW - 1);
        int py0 = min(max(y0, 0), NH - 1), py1 = min(max(y1, 0), NH - 1);
        s_w[tid][0] = (vx0 && vy0) ? wx0 * wy0 : 0.0f;  s_o[tid][0] = py0 * NW + px0;
        s_w[tid][1] = (vx1 && vy0) ? wx1 * wy0 : 0.0f;  s_o[tid][1] = py0 * NW + px1;
        s_w[tid][2] = (vx0 && vy1) ? wx0 * wy1 : 0.0f;  s_o[tid][2] = py1 * NW + px0;
        s_w[tid][3] = (vx1 && vy1) ? wx1 * wy1 : 0.0f;  s_o[tid][3] = py1 * NW + px1;
    }
    __syncthreads();

    // ---- Phase C: 400 (box,corner) pairs over 256 threads + shuffle reduce ----
    const float* fc = feat + (size_t)c * NH * NW;
    float4 acc;
    {
        int n = tid >> 2, k = tid & 3;            // pairs 0..255
        float v = s_w[n][k] * __ldg(fc + s_o[n][k]);
        float4 kv = s_kv[n];
        acc = make_float4(v * kv.x, v * kv.y, v * kv.z, v * kv.w);
    }
    if (tid < 144) {                               // pairs 256..399
        int p = 256 + tid, n = p >> 2, k = p & 3;
        float v = s_w[n][k] * __ldg(fc + s_o[n][k]);
        float4 kv = s_kv[n];
        acc.x += v * kv.x; acc.y += v * kv.y; acc.z += v * kv.z; acc.w += v * kv.w;
    }
    #pragma unroll
    for (int off = 16; off > 0; off >>= 1) {
        acc.x += __shfl_down_sync(0xffffffffu, acc.x, off);
        acc.y += __shfl_down_sync(0xffffffffu, acc.y, off);
        acc.z += __shfl_down_sync(0xffffffffu, acc.z, off);
        acc.w += __shfl_down_sync(0xffffffffu, acc.w, off);
    }
    if ((tid & 31) == 0) red[tid >> 5] = acc;
    __syncthreads();
    if (tid < 8) {
        acc = red[tid];
        #pragma unroll
        for (int off = 4; off > 0; off >>= 1) {
            acc.x += __shfl_down_sync(0x000000ffu, acc.x, off);
            acc.y += __shfl_down_sync(0x000000ffu, acc.y, off);
            acc.z += __shfl_down_sync(0x000000ffu, acc.z, off);
            acc.w += __shfl_down_sync(0x000000ffu, acc.w, off);
        }
        if (tid == 0) s_coef = acc;
    }
    __syncthreads();
    const float A  = s_coef.x;
    const float B1 = s_coef.y;
    const float B2 = s_coef.z;
    const float D  = s_coef.w;

    // ---- Phase D: streaming writer, 8 STG.128/thread ----
    float4* oc = out + (size_t)blockIdx.x * TILE_F4;
    const float w0 = (float)((tid & 63) * 4);
    const float pw0 = (w0      ) * fmaf(w0,       A, -B1);
    const float pw1 = (w0 + 1.f) * fmaf(w0 + 1.f, A, -B1);
    const float pw2 = (w0 + 2.f) * fmaf(w0 + 2.f, A, -B1);
    const float pw3 = (w0 + 3.f) * fmaf(w0 + 3.f, A, -B1);

    #pragma unroll
    for (int k = 0; k < TILE_F4 / 256; k++) {   // 8 iters
        int   i    = k * 256 + tid;
        float hf   = (float)(slice * ROWS_PER_SLICE + (i >> 6));
        float base = fmaf(hf, fmaf(hf, A, -B2), D);
        oc[i] = make_float4(pw0 + base, pw1 + base, pw2 + base, pw3 + base);
    }
}

// ---------------------------------------------------------------------------
extern "C" void kernel_launch(void* const* d_in, const int* in_sizes, int n_in,
                              void* d_out, int out_size) {
    const float* boxes  = (const float*)d_in[0];   // [100,8,3]
    const float* scores = (const float*)d_in[1];   // [100]
    const float* feat   = (const float*)d_in[2];   // [1,256,256,256]

    fused_kernel<<<NC * SLICES, 256>>>(boxes, scores, feat, (float4*)d_out);
    (void)in_sizes; (void)n_in; (void)out_size;
}

// round 17
// speedup vs baseline: 1.1038x; 1.1038x over previous
#include <cuda_runtime.h>
#include <cstdint>

#define NC 256
#define NH 256
#define NW 256
#define NBOX 100
#define SLICES 4                       // writer slices per channel -> 1024 blocks (best measured fused config)
#define ROWS_PER_SLICE (NH / SLICES)   // 64
#define TILE_F4 (ROWS_PER_SLICE * NW / 4)   // 4096 float4 per block

// ---------------------------------------------------------------------------
// ONE kernel, 1024 independent blocks (4 per channel). Each block redundantly
// computes its channel's 4 coefficients (coalesced box staging, 400 gathers
// spread over 256 threads, shuffle reduce), then streams its 64-row slice at
// the L2 write cap. No inter-block sync, one graph node.
//   out[c,h,w] = w*(w*A - B1) + h*(h*A - B2) + D
// nonzero(size=100, fill=0) == each selected box once + (100-cnt) copies of box 0.
// ---------------------------------------------------------------------------
__global__ __launch_bounds__(256)
void fused_kernel(const float* __restrict__ boxes,
                  const float* __restrict__ scores,
                  const float* __restrict__ feat,
                  float4* __restrict__ out) {
    __shared__ float  s_box[NBOX * 24];    // staged box corners (9.6 KB)
    __shared__ float4 s_kv[NBOX];          // per-box (am, am*2cx, am*2cy, am*r2)
    __shared__ float  s_w[NBOX][4];        // bilinear weights
    __shared__ int    s_o[NBOX][4];        // gather offsets
    __shared__ float4 red[8];              // per-warp partials
    __shared__ float4 s_coef;
    __shared__ int    s_pc[4];

    const int tid   = threadIdx.x;
    const int c     = blockIdx.x >> 2;
    const int slice = blockIdx.x & 3;

    // ---- Phase A: scores ballot (warps 0-3) + cooperative box staging ----
    if (tid < 128) {
        int m = (tid < NBOX) ? ((scores[tid] > 0.0f) ? 1 : 0) : 0;
        unsigned bal = __ballot_sync(0xffffffffu, m);
        if ((tid & 31) == 0) s_pc[tid >> 5] = __popc(bal);
    }
    {   // coalesced: 600 float4 staged by all 256 threads
        const float4* src = (const float4*)boxes;
        float4*       dst = (float4*)s_box;
        #pragma unroll
        for (int i = tid; i < NBOX * 6; i += 256) dst[i] = src[i];
    }
    __syncthreads();
    const int cnt = s_pc[0] + s_pc[1] + s_pc[2] + s_pc[3];

    // ---- Phase B: per-box params from smem (threads 0..99) ----
    if (tid < NBOX) {
        const float* b = s_box + tid * 24;
        float lx = b[0], rx = b[0], ly = b[1], ry = b[1];
        #pragma unroll
        for (int k = 1; k < 8; k++) {
            float x = b[3 * k], y = b[3 * k + 1];
            lx = fminf(lx, x); rx = fmaxf(rx, x);
            ly = fminf(ly, y); ry = fmaxf(ry, y);
        }
        float cx  = ((lx + rx) * 0.5f + 128.0f) / 160.0f;
        float cy  = ((ly + ry) * 0.5f + 128.0f) / 160.0f;
        float bev = ((ry - ly) / 160.0f) * ((rx - lx) / 160.0f);
        float a   = 1.0f / (2.0f * bev * bev);

        float m    = (scores[tid] > 0.0f) ? 1.0f : 0.0f;
        float mult = (tid == 0) ? (m + (float)(NBOX - cnt)) : m;
        float am   = a * mult * (1.0f / (float)NBOX);
        s_kv[tid]  = make_float4(am, am * 2.0f * cx, am * 2.0f * cy,
                                 am * (cx * cx + cy * cy));

        // bilinear grid_sample (zero pad, align_corners=False)
        float ix = ((cx + 1.0f) * (float)NW - 1.0f) * 0.5f;
        float iy = ((cy + 1.0f) * (float)NH - 1.0f) * 0.5f;
        float x0f = floorf(ix), y0f = floorf(iy);
        float wx1 = ix - x0f, wx0 = 1.0f - wx1;
        float wy1 = iy - y0f, wy0 = 1.0f - wy1;
        int x0 = (int)x0f, y0 = (int)y0f, x1 = x0 + 1, y1 = y0 + 1;
        bool vx0 = (x0 >= 0 && x0 < NW), vx1 = (x1 >= 0 && x1 < NW);
        bool vy0 = (y0 >= 0 && y0 < NH), vy1 = (y1 >= 0 && y1 < NH);
        int px0 = min(max(x0, 0), NW - 1), px1 = min(max(x1, 0), NW - 1);
        int py0 = min(max(y0, 0), NH - 1), py1 = min(max(y1, 0), NH - 1);
        s_w[tid][0] = (vx0 && vy0) ? wx0 * wy0 : 0.0f;  s_o[tid][0] = py0 * NW + px0;
        s_w[tid][1] = (vx1 && vy0) ? wx1 * wy0 : 0.0f;  s_o[tid][1] = py0 * NW + px1;
        s_w[tid][2] = (vx0 && vy1) ? wx0 * wy1 : 0.0f;  s_o[tid][2] = py1 * NW + px0;
        s_w[tid][3] = (vx1 && vy1) ? wx1 * wy1 : 0.0f;  s_o[tid][3] = py1 * NW + px1;
    }
    __syncthreads();

    // ---- Phase C: 400 (box,corner) pairs over 256 threads + shuffle reduce ----
    const float* fc = feat + (size_t)c * NH * NW;
    float4 acc;
    {
        int n = tid >> 2, k = tid & 3;            // pairs 0..255
        float v = s_w[n][k] * __ldg(fc + s_o[n][k]);
        float4 kv = s_kv[n];
        acc = make_float4(v * kv.x, v * kv.y, v * kv.z, v * kv.w);
    }
    if (tid < 144) {                               // pairs 256..399
        int p = 256 + tid, n = p >> 2, k = p & 3;
        float v = s_w[n][k] * __ldg(fc + s_o[n][k]);
        float4 kv = s_kv[n];
        acc.x += v * kv.x; acc.y += v * kv.y; acc.z += v * kv.z; acc.w += v * kv.w;
    }
    #pragma unroll
    for (int off = 16; off > 0; off >>= 1) {
        acc.x += __shfl_down_sync(0xffffffffu, acc.x, off);
        acc.y += __shfl_down_sync(0xffffffffu, acc.y, off);
        acc.z += __shfl_down_sync(0xffffffffu, acc.z, off);
        acc.w += __shfl_down_sync(0xffffffffu, acc.w, off);
    }
    if ((tid & 31) == 0) red[tid >> 5] = acc;
    __syncthreads();
    if (tid < 8) {
        acc = red[tid];
        #pragma unroll
        for (int off = 4; off > 0; off >>= 1) {
            acc.x += __shfl_down_sync(0x000000ffu, acc.x, off);
            acc.y += __shfl_down_sync(0x000000ffu, acc.y, off);
            acc.z += __shfl_down_sync(0x000000ffu, acc.z, off);
            acc.w += __shfl_down_sync(0x000000ffu, acc.w, off);
        }
        if (tid == 0) s_coef = acc;
    }
    __syncthreads();
    const float A  = s_coef.x;
    const float B1 = s_coef.y;
    const float B2 = s_coef.z;
    const float D  = s_coef.w;

    // ---- Phase D: streaming writer, 16 STG.128/thread ----
    float4* oc = out + (size_t)blockIdx.x * TILE_F4;
    const float w0 = (float)((tid & 63) * 4);
    const float pw0 = (w0      ) * fmaf(w0,       A, -B1);
    const float pw1 = (w0 + 1.f) * fmaf(w0 + 1.f, A, -B1);
    const float pw2 = (w0 + 2.f) * fmaf(w0 + 2.f, A, -B1);
    const float pw3 = (w0 + 3.f) * fmaf(w0 + 3.f, A, -B1);

    #pragma unroll
    for (int k = 0; k < TILE_F4 / 256; k++) {   // 16 iters
        int   i    = k * 256 + tid;
        float hf   = (float)(slice * ROWS_PER_SLICE + (i >> 6));
        float base = fmaf(hf, fmaf(hf, A, -B2), D);
        oc[i] = make_float4(pw0 + base, pw1 + base, pw2 + base, pw3 + base);
    }
}

// ---------------------------------------------------------------------------
extern "C" void kernel_launch(void* const* d_in, const int* in_sizes, int n_in,
                              void* d_out, int out_size) {
    const float* boxes  = (const float*)d_in[0];   // [100,8,3]
    const float* scores = (const float*)d_in[1];   // [100]
    const float* feat   = (const float*)d_in[2];   // [1,256,256,256]

    fused_kernel<<<NC * SLICES, 256>>>(boxes, scores, feat, (float4*)d_out);
    (void)in_sizes; (void)n_in; (void)out_size;
}